// round 11
// baseline (speedup 1.0000x reference)
#include <cuda_runtime.h>
#include <cstdint>

#define CB 16
#define CN 1024
#define CD 512
#define CH 8
#define CKD 64
#define CM (CB * CN)  // 16384
#define LOG2E 1.4426950408889634f

// Scratch (alloc-free rule: __device__ globals)
__device__ float g_xp[(size_t)CM * CD];
__device__ float g_Q[(size_t)CB * CH * CN * CKD];
__device__ float g_K[(size_t)CB * CH * CN * CKD];
__device__ float g_V[(size_t)CB * CH * CN * CKD];
__device__ float g_ctx[(size_t)CM * CD];
__device__ float g_Wt[4 * CD * CD];

// ---------------------------------------------------------------------------
// Helpers
// ---------------------------------------------------------------------------

__device__ __forceinline__ float tf32_rna(float x) {
  uint32_t r;
  asm("cvt.rna.tf32.f32 %0, %1;" : "=r"(r) : "f"(x));
  return __uint_as_float(r);
}

__device__ __forceinline__ float ex2f(float x) {
  float y;
  asm("ex2.approx.f32 %0, %1;" : "=f"(y) : "f"(x));
  return y;
}

__device__ __forceinline__ int perm8(int x) {
  return ((x & 3) << 1) | ((x >> 2) & 1);
}

__device__ __forceinline__ void mma_16n8k8(float* c, const uint32_t* a,
                                           const uint32_t* b) {
  asm volatile(
      "mma.sync.aligned.m16n8k8.row.col.f32.tf32.tf32.f32 "
      "{%0,%1,%2,%3}, {%4,%5,%6,%7}, {%8,%9}, {%0,%1,%2,%3};"
      : "+f"(c[0]), "+f"(c[1]), "+f"(c[2]), "+f"(c[3])
      : "r"(a[0]), "r"(a[1]), "r"(a[2]), "r"(a[3]), "r"(b[0]), "r"(b[1]));
}

__device__ __forceinline__ void cp16(float* dst, const float* src) {
  uint32_t d = (uint32_t)__cvta_generic_to_shared(dst);
  asm volatile("cp.async.cg.shared.global [%0], [%1], 16;" ::"r"(d), "l"(src)
               : "memory");
}
#define CP_COMMIT() asm volatile("cp.async.commit_group;" ::: "memory")
#define CP_WAIT(n) asm volatile("cp.async.wait_group %0;" ::"n"(n) : "memory")

// ---------------------------------------------------------------------------
// Pre-pass: g_xp = tf32(x)
// ---------------------------------------------------------------------------

__global__ void prep_x_kernel(const float* __restrict__ x) {
  size_t i4 = ((size_t)blockIdx.x * 256 + threadIdx.x) * 4;
  float4 v = *(const float4*)(x + i4);
  v.x = tf32_rna(v.x);
  v.y = tf32_rna(v.y);
  v.z = tf32_rna(v.z);
  v.w = tf32_rna(v.w);
  *(float4*)(g_xp + i4) = v;
}

// ---------------------------------------------------------------------------
// Weight transpose: Wt[n][k] = tf32(W[k][n])
// ---------------------------------------------------------------------------

__global__ void transpose_w_kernel(const float* __restrict__ Wq,
                                   const float* __restrict__ Wk,
                                   const float* __restrict__ Wv,
                                   const float* __restrict__ Wo) {
  __shared__ float t[32][33];
  const float* W = (blockIdx.z == 0) ? Wq : (blockIdx.z == 1) ? Wk
                   : (blockIdx.z == 2) ? Wv : Wo;
  float* Out = g_Wt + (size_t)blockIdx.z * CD * CD;
  int n0 = blockIdx.x * 32, k0 = blockIdx.y * 32;
  int tx = threadIdx.x, ty = threadIdx.y;
#pragma unroll
  for (int s = 0; s < 4; s++)
    t[ty + s * 8][tx] = W[(size_t)(k0 + ty + s * 8) * CD + n0 + tx];
  __syncthreads();
#pragma unroll
  for (int s = 0; s < 4; s++)
    Out[(size_t)(n0 + ty + s * 8) * CD + k0 + tx] = tf32_rna(t[tx][ty + s * 8]);
}

// ---------------------------------------------------------------------------
// tf32 mma.sync GEMM (exact R10): pure cp.async staging, 3-stage pipeline
// ---------------------------------------------------------------------------

#define BK 16
#define LDSROW 20
#define GBUF (128 * LDSROW)
#define GEMM_SMEM_BYTES (6 * GBUF * 4)  // 61440 B
#define NKT (CD / BK)                   // 32

__device__ __forceinline__ void gstage(const float* __restrict__ A,
                                       const float* __restrict__ Bt, int row0,
                                       int col0, int kt, float* as, float* bs,
                                       int tid) {
  const int k0 = kt * BK;
#pragma unroll
  for (int it = 0; it < 2; it++) {
    int j = tid + it * 256;
    int row = j >> 2;
    int c4 = (j & 3) * 4;
    cp16(as + row * LDSROW + c4, A + (size_t)(row0 + row) * CD + k0 + c4);
    cp16(bs + row * LDSROW + c4, Bt + (size_t)(col0 + row) * CD + k0 + c4);
  }
  CP_COMMIT();
}

__device__ __forceinline__ void gemm_mma_tile(const float* __restrict__ A,
                                              const float* __restrict__ Bt,
                                              float* __restrict__ Out,
                                              int mode) {
  extern __shared__ float gsm[];
  float* As[3] = {gsm, gsm + GBUF, gsm + 2 * GBUF};
  float* Bs[3] = {gsm + 3 * GBUF, gsm + 4 * GBUF, gsm + 5 * GBUF};

  const int tid = threadIdx.x;
  const int lane = tid & 31;
  const int warp = tid >> 5;
  const int wm = warp & 3;
  const int wn = warp >> 2;
  const int g = lane >> 2;
  const int tg = lane & 3;

  const int col0 = blockIdx.x * 128;
  const int row0 = blockIdx.y * 128;

  float acc[2][8][4];
#pragma unroll
  for (int mt = 0; mt < 2; mt++)
#pragma unroll
    for (int nt = 0; nt < 8; nt++)
#pragma unroll
      for (int i = 0; i < 4; i++) acc[mt][nt][i] = 0.f;

  gstage(A, Bt, row0, col0, 0, As[0], Bs[0], tid);
  gstage(A, Bt, row0, col0, 1, As[1], Bs[1], tid);

  for (int kt = 0; kt < NKT; kt++) {
    const int buf = kt % 3;
    if (kt < NKT - 1) { CP_WAIT(1); } else { CP_WAIT(0); }
    __syncthreads();
    if (kt + 2 < NKT)
      gstage(A, Bt, row0, col0, kt + 2, As[(kt + 2) % 3], Bs[(kt + 2) % 3], tid);

    const uint32_t* asu = (const uint32_t*)As[buf];
    const uint32_t* bsu = (const uint32_t*)Bs[buf];
#pragma unroll
    for (int k8 = 0; k8 < 2; k8++) {
      const int kb = k8 * 8 + tg;
      uint32_t af[2][4];
#pragma unroll
      for (int mt = 0; mt < 2; mt++) {
        int r = wm * 32 + mt * 16 + g;
        af[mt][0] = asu[r * LDSROW + kb];
        af[mt][1] = asu[(r + 8) * LDSROW + kb];
        af[mt][2] = asu[r * LDSROW + kb + 4];
        af[mt][3] = asu[(r + 8) * LDSROW + kb + 4];
      }
#pragma unroll
      for (int nt = 0; nt < 8; nt++) {
        int n = wn * 64 + nt * 8 + g;
        uint32_t bf[2];
        bf[0] = bsu[n * LDSROW + kb];
        bf[1] = bsu[n * LDSROW + kb + 4];
        mma_16n8k8(acc[0][nt], af[0], bf);
        mma_16n8k8(acc[1][nt], af[1], bf);
      }
    }
  }
  __syncthreads();

  const float qs = 0.125f * LOG2E;
#pragma unroll
  for (int mt = 0; mt < 2; mt++) {
#pragma unroll
    for (int nt = 0; nt < 8; nt++) {
      int R = row0 + wm * 32 + mt * 16 + g;
      int C = col0 + wn * 64 + nt * 8 + 2 * tg;
      float2 v0 = make_float2(acc[mt][nt][0], acc[mt][nt][1]);
      float2 v1 = make_float2(acc[mt][nt][2], acc[mt][nt][3]);
      if (mode <= 1) {
        int h = C >> 6, dr = C & 63;
        int d0 = (dr & ~7) | perm8(dr & 7);
        int d1 = (dr & ~7) | perm8((dr & 7) + 1);
        if (mode == 0) {
          v0.x *= qs; v0.y *= qs; v1.x *= qs; v1.y *= qs;
        }
        int bb0 = R >> 10, n0 = R & 1023;
        int bb1 = (R + 8) >> 10, n1 = (R + 8) & 1023;
        size_t b0 = (((size_t)bb0 * CH + h) * CN + n0) * CKD;
        size_t b1 = (((size_t)bb1 * CH + h) * CN + n1) * CKD;
        Out[b0 + d0] = tf32_rna(v0.x);
        Out[b0 + d1] = tf32_rna(v0.y);
        Out[b1 + d0] = tf32_rna(v1.x);
        Out[b1 + d1] = tf32_rna(v1.y);
      } else if (mode == 2) {
        int h = C >> 6, d = C & 63;
        int bb = R >> 10, nn = R & 1023;
        int colp = (nn & ~7) | perm8(nn & 7);
        size_t base = (((size_t)bb * CH + h) * CKD + d) * CN;
        Out[base + colp] = tf32_rna(v0.x);
        Out[base + CN + colp] = tf32_rna(v0.y);
        Out[base + colp + 8] = tf32_rna(v1.x);
        Out[base + CN + colp + 8] = tf32_rna(v1.y);
      } else {
        *(float2*)(Out + (size_t)R * CD + C) = v0;
        *(float2*)(Out + (size_t)(R + 8) * CD + C) = v1;
      }
    }
  }
}

__global__ __launch_bounds__(256, 2) void qkv_mma_kernel(void) {
  const float* Bt = g_Wt + (size_t)blockIdx.z * CD * CD;
  float* Out = (blockIdx.z == 0) ? g_Q : (blockIdx.z == 1) ? g_K : g_V;
  gemm_mma_tile(g_xp, Bt, Out, (int)blockIdx.z);
}

__global__ __launch_bounds__(256, 2) void out_mma_kernel(float* __restrict__ out) {
  gemm_mma_tile(g_ctx, g_Wt + (size_t)3 * CD * CD, out, 3);
}

// ---------------------------------------------------------------------------
// mma.sync flash attention: 128 threads / 4 warps, warp tile m32 (2 x m16).
// K/V fragment loads shared across both m-tiles -> L1 ops per MMA down 29%.
// ---------------------------------------------------------------------------

#define KVSTRIDE 72
#define QSMF (128 * KVSTRIDE)
#define KVT (64 * KVSTRIDE)
#define ATTN_SMEM_BYTES ((QSMF + 4 * KVT) * 4)  // 110592 B

__device__ __forceinline__ void stage_kv(const float* __restrict__ Kg,
                                         const float* __restrict__ Vtg,
                                         float* kdst, float* vdst, int kb,
                                         int tid) {
#pragma unroll
  for (int it = 0; it < 8; it++) {
    int j = tid + it * 128;
    int row = j >> 4;
    int c4 = (j & 15) * 4;
    cp16(kdst + row * KVSTRIDE + c4, Kg + (size_t)(kb * 64 + row) * CKD + c4);
    cp16(vdst + row * KVSTRIDE + c4, Vtg + (size_t)row * CN + kb * 64 + c4);
  }
  CP_COMMIT();
}

__global__ __launch_bounds__(128, 2) void attn_mma_kernel(
    const float* __restrict__ bias, const float* __restrict__ bias_scale) {
  extern __shared__ float sm[];
  float* Qs = sm;
  float* Kbuf[2] = {sm + QSMF, sm + QSMF + 2 * KVT};
  float* Vbuf[2] = {sm + QSMF + KVT, sm + QSMF + 3 * KVT};

  const int qb = blockIdx.x;
  const int h = blockIdx.y;
  const int b = blockIdx.z;
  const int tid = threadIdx.x;
  const int lane = tid & 31;
  const int warp = tid >> 5;  // 0..3
  const int g = lane >> 2;
  const int tg = lane & 3;
  const int m0 = warp * 32;

  const float bscale = bias_scale[h] * LOG2E;
  const float* Qg = g_Q + (((size_t)b * CH + h) * CN + (size_t)qb * 128) * CKD;
  const float* Kg = g_K + ((size_t)b * CH + h) * CN * CKD;
  const float* Vtg = g_V + ((size_t)b * CH + h) * CKD * CN;

  // stage Q: 2048 float4 with 128 threads
#pragma unroll
  for (int it = 0; it < 16; it++) {
    int j = tid + it * 128;
    int row = j >> 4;
    int c4 = (j & 15) * 4;
    *(float4*)(Qs + row * KVSTRIDE + c4) =
        *(const float4*)(Qg + (size_t)row * CKD + c4);
  }
  stage_kv(Kg, Vtg, Kbuf[0], Vbuf[0], 0, tid);
  __syncthreads();

  float oacc[2][8][4];
#pragma unroll
  for (int mt = 0; mt < 2; mt++)
#pragma unroll
    for (int t = 0; t < 8; t++)
#pragma unroll
      for (int c = 0; c < 4; c++) oacc[mt][t][c] = 0.f;
  float m_i[2][2] = {{-1e30f, -1e30f}, {-1e30f, -1e30f}};
  float l_i[2][2] = {{0.f, 0.f}, {0.f, 0.f}};

  const float2* qp = (const float2*)Qs;
  const int qr00 = (m0 + g) * (KVSTRIDE / 2);
  const int qr01 = (m0 + 8 + g) * (KVSTRIDE / 2);
  const int qr10 = (m0 + 16 + g) * (KVSTRIDE / 2);
  const int qr11 = (m0 + 24 + g) * (KVSTRIDE / 2);

  for (int kb = 0; kb < 16; kb++) {
    const int buf = kb & 1;
    if (kb + 1 < 16)
      stage_kv(Kg, Vtg, Kbuf[buf ^ 1], Vbuf[buf ^ 1], kb + 1, tid);
    if (kb + 1 < 16) { CP_WAIT(1); } else { CP_WAIT(0); }
    __syncthreads();

    const float2* kp = (const float2*)Kbuf[buf];
    const float2* vp = (const float2*)Vbuf[buf];

    float sacc[2][8][4];
#pragma unroll
    for (int mt = 0; mt < 2; mt++)
#pragma unroll
      for (int t = 0; t < 8; t++)
#pragma unroll
        for (int c = 0; c < 4; c++) sacc[mt][t][c] = 0.f;

    // --- S = Q K^T: K fragment shared by both m-tiles ---
#pragma unroll
    for (int j = 0; j < 8; j++) {
      float2 qa0 = qp[qr00 + j * 4 + tg];
      float2 qa1 = qp[qr01 + j * 4 + tg];
      float2 qb0 = qp[qr10 + j * 4 + tg];
      float2 qb1 = qp[qr11 + j * 4 + tg];
      uint32_t af0[4] = {__float_as_uint(qa0.x), __float_as_uint(qa1.x),
                         __float_as_uint(qa0.y), __float_as_uint(qa1.y)};
      uint32_t af1[4] = {__float_as_uint(qb0.x), __float_as_uint(qb1.x),
                         __float_as_uint(qb0.y), __float_as_uint(qb1.y)};
#pragma unroll
      for (int t = 0; t < 8; t++) {
        float2 kv = kp[(t * 8 + g) * (KVSTRIDE / 2) + j * 4 + tg];
        uint32_t bf[2] = {__float_as_uint(kv.x), __float_as_uint(kv.y)};
        mma_16n8k8(sacc[0][t], af0, bf);
        mma_16n8k8(sacc[1][t], af1, bf);
      }
    }

    // --- bias + online softmax per m-tile ---
#pragma unroll
    for (int mt = 0; mt < 2; mt++) {
      const int q0 = qb * 128 + m0 + mt * 16 + g;
      const float* bp = bias + (size_t)q0 * CN + kb * 64;
      float mnew0 = -1e30f, mnew1 = -1e30f;
#pragma unroll
      for (int t = 0; t < 8; t++) {
        float2 bv0 = *(const float2*)(bp + t * 8 + 2 * tg);
        float2 bv1 = *(const float2*)(bp + (size_t)8 * CN + t * 8 + 2 * tg);
        sacc[mt][t][0] = fmaf(bv0.x, bscale, sacc[mt][t][0]);
        sacc[mt][t][1] = fmaf(bv0.y, bscale, sacc[mt][t][1]);
        sacc[mt][t][2] = fmaf(bv1.x, bscale, sacc[mt][t][2]);
        sacc[mt][t][3] = fmaf(bv1.y, bscale, sacc[mt][t][3]);
        mnew0 = fmaxf(mnew0, fmaxf(sacc[mt][t][0], sacc[mt][t][1]));
        mnew1 = fmaxf(mnew1, fmaxf(sacc[mt][t][2], sacc[mt][t][3]));
      }
#pragma unroll
      for (int off = 1; off <= 2; off <<= 1) {
        mnew0 = fmaxf(mnew0, __shfl_xor_sync(0xffffffffu, mnew0, off));
        mnew1 = fmaxf(mnew1, __shfl_xor_sync(0xffffffffu, mnew1, off));
      }
      float mn0 = fmaxf(m_i[mt][0], mnew0);
      float mn1 = fmaxf(m_i[mt][1], mnew1);
      float corr0 = ex2f(m_i[mt][0] - mn0);
      float corr1 = ex2f(m_i[mt][1] - mn1);
      m_i[mt][0] = mn0;
      m_i[mt][1] = mn1;

      float rs0 = 0.f, rs1 = 0.f;
#pragma unroll
      for (int t = 0; t < 8; t++) {
        sacc[mt][t][0] = ex2f(sacc[mt][t][0] - mn0);
        sacc[mt][t][1] = ex2f(sacc[mt][t][1] - mn0);
        sacc[mt][t][2] = ex2f(sacc[mt][t][2] - mn1);
        sacc[mt][t][3] = ex2f(sacc[mt][t][3] - mn1);
        rs0 += sacc[mt][t][0] + sacc[mt][t][1];
        rs1 += sacc[mt][t][2] + sacc[mt][t][3];
      }
#pragma unroll
      for (int off = 1; off <= 2; off <<= 1) {
        rs0 += __shfl_xor_sync(0xffffffffu, rs0, off);
        rs1 += __shfl_xor_sync(0xffffffffu, rs1, off);
      }
      l_i[mt][0] = l_i[mt][0] * corr0 + rs0;
      l_i[mt][1] = l_i[mt][1] * corr1 + rs1;

#pragma unroll
      for (int t = 0; t < 8; t++) {
        oacc[mt][t][0] *= corr0; oacc[mt][t][1] *= corr0;
        oacc[mt][t][2] *= corr1; oacc[mt][t][3] *= corr1;
      }
    }

    // --- O += P V: V fragment shared by both m-tiles ---
    const int srcA = (lane & ~3) | (tg >> 1);
    const int srcB = srcA + 2;
    const bool odd = (tg & 1);
#pragma unroll
    for (int j = 0; j < 8; j++) {
      uint32_t af[2][4];
#pragma unroll
      for (int mt = 0; mt < 2; mt++) {
        uint32_t p0 = __float_as_uint(sacc[mt][j][0]);
        uint32_t p1 = __float_as_uint(sacc[mt][j][1]);
        uint32_t p2 = __float_as_uint(sacc[mt][j][2]);
        uint32_t p3 = __float_as_uint(sacc[mt][j][3]);
        uint32_t t0 = __shfl_sync(0xffffffffu, p0, srcA);
        uint32_t t1 = __shfl_sync(0xffffffffu, p1, srcA);
        uint32_t t2 = __shfl_sync(0xffffffffu, p2, srcA);
        uint32_t t3 = __shfl_sync(0xffffffffu, p3, srcA);
        uint32_t t4 = __shfl_sync(0xffffffffu, p0, srcB);
        uint32_t t5 = __shfl_sync(0xffffffffu, p1, srcB);
        uint32_t t6 = __shfl_sync(0xffffffffu, p2, srcB);
        uint32_t t7 = __shfl_sync(0xffffffffu, p3, srcB);
        af[mt][0] = odd ? t1 : t0;
        af[mt][1] = odd ? t3 : t2;
        af[mt][2] = odd ? t5 : t4;
        af[mt][3] = odd ? t7 : t6;
      }
#pragma unroll
      for (int t = 0; t < 8; t++) {
        float2 vv = vp[(t * 8 + g) * (KVSTRIDE / 2) + j * 4 + tg];
        uint32_t bf[2] = {__float_as_uint(vv.x), __float_as_uint(vv.y)};
        mma_16n8k8(oacc[0][t], af[0], bf);
        mma_16n8k8(oacc[1][t], af[1], bf);
      }
    }
    __syncthreads();
  }

  // --- Epilogue per m-tile: ctx = tf32(O / l), coalesced float2 stores ---
#pragma unroll
  for (int mt = 0; mt < 2; mt++) {
    const int q0 = qb * 128 + m0 + mt * 16 + g;
    float inv0 = 1.f / l_i[mt][0];
    float inv1 = 1.f / l_i[mt][1];
    float* cp0 = g_ctx + ((size_t)b * CN + q0) * CD + h * CKD;
#pragma unroll
    for (int t = 0; t < 8; t++) {
      *(float2*)(cp0 + t * 8 + 2 * tg) =
          make_float2(tf32_rna(oacc[mt][t][0] * inv0),
                      tf32_rna(oacc[mt][t][1] * inv0));
      *(float2*)(cp0 + (size_t)8 * CD + t * 8 + 2 * tg) =
          make_float2(tf32_rna(oacc[mt][t][2] * inv1),
                      tf32_rna(oacc[mt][t][3] * inv1));
    }
  }
}

// ---------------------------------------------------------------------------

extern "C" void kernel_launch(void* const* d_in, const int* in_sizes, int n_in,
                              void* d_out, int out_size) {
  const float* x = (const float*)d_in[0];
  const float* leadlag_bias = (const float*)d_in[1];
  const float* Wq = (const float*)d_in[2];
  const float* Wk = (const float*)d_in[3];
  const float* Wv = (const float*)d_in[4];
  const float* Wo = (const float*)d_in[5];
  const float* bias_scale = (const float*)d_in[6];
  float* out = (float*)d_out;

  (void)in_sizes; (void)n_in; (void)out_size;

  static int attr_set = 0;
  if (!attr_set) {
    cudaFuncSetAttribute(attn_mma_kernel,
                         cudaFuncAttributeMaxDynamicSharedMemorySize,
                         ATTN_SMEM_BYTES);
    cudaFuncSetAttribute(qkv_mma_kernel,
                         cudaFuncAttributeMaxDynamicSharedMemorySize,
                         GEMM_SMEM_BYTES);
    cudaFuncSetAttribute(out_mma_kernel,
                         cudaFuncAttributeMaxDynamicSharedMemorySize,
                         GEMM_SMEM_BYTES);
    attr_set = 1;
  }

  prep_x_kernel<<<CM * CD / 1024, 256>>>(x);
  transpose_w_kernel<<<dim3(CD / 32, CD / 32, 4), dim3(32, 8)>>>(Wq, Wk, Wv, Wo);
  qkv_mma_kernel<<<dim3(CD / 128, CM / 128, 3), 256, GEMM_SMEM_BYTES>>>();
  attn_mma_kernel<<<dim3(CN / 128, CH, CB), 128, ATTN_SMEM_BYTES>>>(
      leadlag_bias, bias_scale);
  out_mma_kernel<<<dim3(CD / 128, CM / 128, 1), 256, GEMM_SMEM_BYTES>>>(out);
}

// round 16
// speedup vs baseline: 1.0651x; 1.0651x over previous
#include <cuda_runtime.h>
#include <cstdint>

#define CB 16
#define CN 1024
#define CD 512
#define CH 8
#define CKD 64
#define CM (CB * CN)  // 16384
#define LOG2E 1.4426950408889634f

// Scratch (alloc-free rule: __device__ globals)
__device__ float g_xp[(size_t)CM * CD];
__device__ float g_Q[(size_t)CB * CH * CN * CKD];
__device__ float g_K[(size_t)CB * CH * CN * CKD];
__device__ float g_V[(size_t)CB * CH * CN * CKD];  // Vt [b,h][d][n] UNpermuted
__device__ float g_ctx[(size_t)CM * CD];
__device__ float g_Wt[4 * CD * CD];

// ---------------------------------------------------------------------------
// Helpers
// ---------------------------------------------------------------------------

__device__ __forceinline__ float tf32_rna(float x) {
  uint32_t r;
  asm("cvt.rna.tf32.f32 %0, %1;" : "=r"(r) : "f"(x));
  return __uint_as_float(r);
}

__device__ __forceinline__ float ex2f(float x) {
  float y;
  asm("ex2.approx.f32 %0, %1;" : "=f"(y) : "f"(x));
  return y;
}

__device__ __forceinline__ int perm8(int x) {
  return ((x & 3) << 1) | ((x >> 2) & 1);
}

__device__ __forceinline__ void mma_16n8k8(float* c, const uint32_t* a,
                                           const uint32_t* b) {
  asm volatile(
      "mma.sync.aligned.m16n8k8.row.col.f32.tf32.tf32.f32 "
      "{%0,%1,%2,%3}, {%4,%5,%6,%7}, {%8,%9}, {%0,%1,%2,%3};"
      : "+f"(c[0]), "+f"(c[1]), "+f"(c[2]), "+f"(c[3])
      : "r"(a[0]), "r"(a[1]), "r"(a[2]), "r"(a[3]), "r"(b[0]), "r"(b[1]));
}

__device__ __forceinline__ void cp16(float* dst, const float* src) {
  uint32_t d = (uint32_t)__cvta_generic_to_shared(dst);
  asm volatile("cp.async.cg.shared.global [%0], [%1], 16;" ::"r"(d), "l"(src)
               : "memory");
}
#define CP_COMMIT() asm volatile("cp.async.commit_group;" ::: "memory")
#define CP_WAIT(n) asm volatile("cp.async.wait_group %0;" ::"n"(n) : "memory")

// ---------------------------------------------------------------------------
// Pre-pass: g_xp = tf32(x)
// ---------------------------------------------------------------------------

__global__ void prep_x_kernel(const float* __restrict__ x) {
  size_t i4 = ((size_t)blockIdx.x * 256 + threadIdx.x) * 4;
  float4 v = *(const float4*)(x + i4);
  v.x = tf32_rna(v.x);
  v.y = tf32_rna(v.y);
  v.z = tf32_rna(v.z);
  v.w = tf32_rna(v.w);
  *(float4*)(g_xp + i4) = v;
}

// ---------------------------------------------------------------------------
// Weight transpose: Wt[n][k] = tf32(W[k][n])
// ---------------------------------------------------------------------------

__global__ void transpose_w_kernel(const float* __restrict__ Wq,
                                   const float* __restrict__ Wk,
                                   const float* __restrict__ Wv,
                                   const float* __restrict__ Wo) {
  __shared__ float t[32][33];
  const float* W = (blockIdx.z == 0) ? Wq : (blockIdx.z == 1) ? Wk
                   : (blockIdx.z == 2) ? Wv : Wo;
  float* Out = g_Wt + (size_t)blockIdx.z * CD * CD;
  int n0 = blockIdx.x * 32, k0 = blockIdx.y * 32;
  int tx = threadIdx.x, ty = threadIdx.y;
#pragma unroll
  for (int s = 0; s < 4; s++)
    t[ty + s * 8][tx] = W[(size_t)(k0 + ty + s * 8) * CD + n0 + tx];
  __syncthreads();
#pragma unroll
  for (int s = 0; s < 4; s++)
    Out[(size_t)(n0 + ty + s * 8) * CD + k0 + tx] = tf32_rna(t[tx][ty + s * 8]);
}

// ---------------------------------------------------------------------------
// tf32 mma.sync GEMM (exact R10): pure cp.async staging, 3-stage pipeline
// ---------------------------------------------------------------------------

#define BK 16
#define LDSROW 20
#define GBUF (128 * LDSROW)
#define GEMM_SMEM_BYTES (6 * GBUF * 4)  // 61440 B
#define NKT (CD / BK)                   // 32

__device__ __forceinline__ void gstage(const float* __restrict__ A,
                                       const float* __restrict__ Bt, int row0,
                                       int col0, int kt, float* as, float* bs,
                                       int tid) {
  const int k0 = kt * BK;
#pragma unroll
  for (int it = 0; it < 2; it++) {
    int j = tid + it * 256;
    int row = j >> 2;
    int c4 = (j & 3) * 4;
    cp16(as + row * LDSROW + c4, A + (size_t)(row0 + row) * CD + k0 + c4);
    cp16(bs + row * LDSROW + c4, Bt + (size_t)(col0 + row) * CD + k0 + c4);
  }
  CP_COMMIT();
}

__device__ __forceinline__ void gemm_mma_tile(const float* __restrict__ A,
                                              const float* __restrict__ Bt,
                                              float* __restrict__ Out,
                                              int mode) {
  extern __shared__ float gsm[];
  float* As[3] = {gsm, gsm + GBUF, gsm + 2 * GBUF};
  float* Bs[3] = {gsm + 3 * GBUF, gsm + 4 * GBUF, gsm + 5 * GBUF};

  const int tid = threadIdx.x;
  const int lane = tid & 31;
  const int warp = tid >> 5;
  const int wm = warp & 3;
  const int wn = warp >> 2;
  const int g = lane >> 2;
  const int tg = lane & 3;

  const int col0 = blockIdx.x * 128;
  const int row0 = blockIdx.y * 128;

  float acc[2][8][4];
#pragma unroll
  for (int mt = 0; mt < 2; mt++)
#pragma unroll
    for (int nt = 0; nt < 8; nt++)
#pragma unroll
      for (int i = 0; i < 4; i++) acc[mt][nt][i] = 0.f;

  gstage(A, Bt, row0, col0, 0, As[0], Bs[0], tid);
  gstage(A, Bt, row0, col0, 1, As[1], Bs[1], tid);

  for (int kt = 0; kt < NKT; kt++) {
    const int buf = kt % 3;
    if (kt < NKT - 1) { CP_WAIT(1); } else { CP_WAIT(0); }
    __syncthreads();
    if (kt + 2 < NKT)
      gstage(A, Bt, row0, col0, kt + 2, As[(kt + 2) % 3], Bs[(kt + 2) % 3], tid);

    const uint32_t* asu = (const uint32_t*)As[buf];
    const uint32_t* bsu = (const uint32_t*)Bs[buf];
#pragma unroll
    for (int k8 = 0; k8 < 2; k8++) {
      const int kb = k8 * 8 + tg;
      uint32_t af[2][4];
#pragma unroll
      for (int mt = 0; mt < 2; mt++) {
        int r = wm * 32 + mt * 16 + g;
        af[mt][0] = asu[r * LDSROW + kb];
        af[mt][1] = asu[(r + 8) * LDSROW + kb];
        af[mt][2] = asu[r * LDSROW + kb + 4];
        af[mt][3] = asu[(r + 8) * LDSROW + kb + 4];
      }
#pragma unroll
      for (int nt = 0; nt < 8; nt++) {
        int n = wn * 64 + nt * 8 + g;
        uint32_t bf[2];
        bf[0] = bsu[n * LDSROW + kb];
        bf[1] = bsu[n * LDSROW + kb + 4];
        mma_16n8k8(acc[0][nt], af[0], bf);
        mma_16n8k8(acc[1][nt], af[1], bf);
      }
    }
  }
  __syncthreads();

  const float qs = 0.125f * LOG2E;
#pragma unroll
  for (int mt = 0; mt < 2; mt++) {
#pragma unroll
    for (int nt = 0; nt < 8; nt++) {
      int R = row0 + wm * 32 + mt * 16 + g;
      int C = col0 + wn * 64 + nt * 8 + 2 * tg;
      float2 v0 = make_float2(acc[mt][nt][0], acc[mt][nt][1]);
      float2 v1 = make_float2(acc[mt][nt][2], acc[mt][nt][3]);
      if (mode <= 1) {  // Q or K -> [b,h,n,d'] with d' permuted
        int h = C >> 6, dr = C & 63;
        int d0 = (dr & ~7) | perm8(dr & 7);
        int d1 = (dr & ~7) | perm8((dr & 7) + 1);
        if (mode == 0) {
          v0.x *= qs; v0.y *= qs; v1.x *= qs; v1.y *= qs;
        }
        int bb0 = R >> 10, n0 = R & 1023;
        int bb1 = (R + 8) >> 10, n1 = (R + 8) & 1023;
        size_t b0 = (((size_t)bb0 * CH + h) * CN + n0) * CKD;
        size_t b1 = (((size_t)bb1 * CH + h) * CN + n1) * CKD;
        Out[b0 + d0] = tf32_rna(v0.x);
        Out[b0 + d1] = tf32_rna(v0.y);
        Out[b1 + d0] = tf32_rna(v1.x);
        Out[b1 + d1] = tf32_rna(v1.y);
      } else if (mode == 2) {  // V -> Vt [b,h][d][n]  (UNpermuted n)
        int h = C >> 6, d = C & 63;
        int bb = R >> 10, nn = R & 1023;
        size_t base = (((size_t)bb * CH + h) * CKD + d) * CN;
        Out[base + nn] = tf32_rna(v0.x);
        Out[base + CN + nn] = tf32_rna(v0.y);
        Out[base + nn + 8] = tf32_rna(v1.x);
        Out[base + CN + nn + 8] = tf32_rna(v1.y);
      } else {  // plain row-major (final output)
        *(float2*)(Out + (size_t)R * CD + C) = v0;
        *(float2*)(Out + (size_t)(R + 8) * CD + C) = v1;
      }
    }
  }
}

__global__ __launch_bounds__(256, 2) void qkv_mma_kernel(void) {
  const float* Bt = g_Wt + (size_t)blockIdx.z * CD * CD;
  float* Out = (blockIdx.z == 0) ? g_Q : (blockIdx.z == 1) ? g_K : g_V;
  gemm_mma_tile(g_xp, Bt, Out, (int)blockIdx.z);
}

__global__ __launch_bounds__(256, 2) void out_mma_kernel(float* __restrict__ out) {
  gemm_mma_tile(g_ctx, g_Wt + (size_t)3 * CD * CD, out, 3);
}

// ---------------------------------------------------------------------------
// mma.sync flash attention: 128 threads / 4 warps, warp tile m32.
// PV A-fragment taken DIRECTLY from S accumulator ({c0,c2,c1,c3}); the
// fragment-k ordering is perm8, matched by plain float2 loads from the
// UNpermuted Vt layout. No shuffles, no P rounding pass.
// ---------------------------------------------------------------------------

#define KVSTRIDE 72
#define QSMF (128 * KVSTRIDE)
#define KVT (64 * KVSTRIDE)
#define ATTN_SMEM_BYTES ((QSMF + 4 * KVT) * 4)  // 110592 B

__device__ __forceinline__ void stage_kv(const float* __restrict__ Kg,
                                         const float* __restrict__ Vtg,
                                         float* kdst, float* vdst, int kb,
                                         int tid) {
#pragma unroll
  for (int it = 0; it < 8; it++) {
    int j = tid + it * 128;
    int row = j >> 4;
    int c4 = (j & 15) * 4;
    cp16(kdst + row * KVSTRIDE + c4, Kg + (size_t)(kb * 64 + row) * CKD + c4);
    cp16(vdst + row * KVSTRIDE + c4, Vtg + (size_t)row * CN + kb * 64 + c4);
  }
  CP_COMMIT();
}

__global__ __launch_bounds__(128, 2) void attn_mma_kernel(
    const float* __restrict__ bias, const float* __restrict__ bias_scale) {
  extern __shared__ float sm[];
  float* Qs = sm;
  float* Kbuf[2] = {sm + QSMF, sm + QSMF + 2 * KVT};
  float* Vbuf[2] = {sm + QSMF + KVT, sm + QSMF + 3 * KVT};

  const int qb = blockIdx.x;
  const int h = blockIdx.y;
  const int b = blockIdx.z;
  const int tid = threadIdx.x;
  const int lane = tid & 31;
  const int warp = tid >> 5;  // 0..3
  const int g = lane >> 2;
  const int tg = lane & 3;
  const int m0 = warp * 32;

  const float bscale = bias_scale[h] * LOG2E;
  const float* Qg = g_Q + (((size_t)b * CH + h) * CN + (size_t)qb * 128) * CKD;
  const float* Kg = g_K + ((size_t)b * CH + h) * CN * CKD;
  const float* Vtg = g_V + ((size_t)b * CH + h) * CKD * CN;

#pragma unroll
  for (int it = 0; it < 16; it++) {
    int j = tid + it * 128;
    int row = j >> 4;
    int c4 = (j & 15) * 4;
    *(float4*)(Qs + row * KVSTRIDE + c4) =
        *(const float4*)(Qg + (size_t)row * CKD + c4);
  }
  stage_kv(Kg, Vtg, Kbuf[0], Vbuf[0], 0, tid);
  __syncthreads();

  float oacc[2][8][4];
#pragma unroll
  for (int mt = 0; mt < 2; mt++)
#pragma unroll
    for (int t = 0; t < 8; t++)
#pragma unroll
      for (int c = 0; c < 4; c++) oacc[mt][t][c] = 0.f;
  float m_i[2][2] = {{-1e30f, -1e30f}, {-1e30f, -1e30f}};
  float l_i[2][2] = {{0.f, 0.f}, {0.f, 0.f}};

  const float2* qp = (const float2*)Qs;
  const int qr00 = (m0 + g) * (KVSTRIDE / 2);
  const int qr01 = (m0 + 8 + g) * (KVSTRIDE / 2);
  const int qr10 = (m0 + 16 + g) * (KVSTRIDE / 2);
  const int qr11 = (m0 + 24 + g) * (KVSTRIDE / 2);

  for (int kb = 0; kb < 16; kb++) {
    const int buf = kb & 1;
    if (kb + 1 < 16)
      stage_kv(Kg, Vtg, Kbuf[buf ^ 1], Vbuf[buf ^ 1], kb + 1, tid);
    if (kb + 1 < 16) { CP_WAIT(1); } else { CP_WAIT(0); }
    __syncthreads();

    const float2* kp = (const float2*)Kbuf[buf];
    const float2* vp = (const float2*)Vbuf[buf];

    float sacc[2][8][4];
#pragma unroll
    for (int mt = 0; mt < 2; mt++)
#pragma unroll
      for (int t = 0; t < 8; t++)
#pragma unroll
        for (int c = 0; c < 4; c++) sacc[mt][t][c] = 0.f;

    // --- S = Q K^T: K fragment shared by both m-tiles ---
#pragma unroll
    for (int j = 0; j < 8; j++) {
      float2 qa0 = qp[qr00 + j * 4 + tg];
      float2 qa1 = qp[qr01 + j * 4 + tg];
      float2 qb0 = qp[qr10 + j * 4 + tg];
      float2 qb1 = qp[qr11 + j * 4 + tg];
      uint32_t af0[4] = {__float_as_uint(qa0.x), __float_as_uint(qa1.x),
                         __float_as_uint(qa0.y), __float_as_uint(qa1.y)};
      uint32_t af1[4] = {__float_as_uint(qb0.x), __float_as_uint(qb1.x),
                         __float_as_uint(qb0.y), __float_as_uint(qb1.y)};
#pragma unroll
      for (int t = 0; t < 8; t++) {
        float2 kv = kp[(t * 8 + g) * (KVSTRIDE / 2) + j * 4 + tg];
        uint32_t bf[2] = {__float_as_uint(kv.x), __float_as_uint(kv.y)};
        mma_16n8k8(sacc[0][t], af0, bf);
        mma_16n8k8(sacc[1][t], af1, bf);
      }
    }

    // --- bias + online softmax per m-tile ---
#pragma unroll
    for (int mt = 0; mt < 2; mt++) {
      const int q0 = qb * 128 + m0 + mt * 16 + g;
      const float* bp = bias + (size_t)q0 * CN + kb * 64;
      float mnew0 = -1e30f, mnew1 = -1e30f;
#pragma unroll
      for (int t = 0; t < 8; t++) {
        float2 bv0 = *(const float2*)(bp + t * 8 + 2 * tg);
        float2 bv1 = *(const float2*)(bp + (size_t)8 * CN + t * 8 + 2 * tg);
        sacc[mt][t][0] = fmaf(bv0.x, bscale, sacc[mt][t][0]);
        sacc[mt][t][1] = fmaf(bv0.y, bscale, sacc[mt][t][1]);
        sacc[mt][t][2] = fmaf(bv1.x, bscale, sacc[mt][t][2]);
        sacc[mt][t][3] = fmaf(bv1.y, bscale, sacc[mt][t][3]);
        mnew0 = fmaxf(mnew0, fmaxf(sacc[mt][t][0], sacc[mt][t][1]));
        mnew1 = fmaxf(mnew1, fmaxf(sacc[mt][t][2], sacc[mt][t][3]));
      }
#pragma unroll
      for (int off = 1; off <= 2; off <<= 1) {
        mnew0 = fmaxf(mnew0, __shfl_xor_sync(0xffffffffu, mnew0, off));
        mnew1 = fmaxf(mnew1, __shfl_xor_sync(0xffffffffu, mnew1, off));
      }
      float mn0 = fmaxf(m_i[mt][0], mnew0);
      float mn1 = fmaxf(m_i[mt][1], mnew1);
      float corr0 = ex2f(m_i[mt][0] - mn0);
      float corr1 = ex2f(m_i[mt][1] - mn1);
      m_i[mt][0] = mn0;
      m_i[mt][1] = mn1;

      float rs0 = 0.f, rs1 = 0.f;
#pragma unroll
      for (int t = 0; t < 8; t++) {
        sacc[mt][t][0] = ex2f(sacc[mt][t][0] - mn0);
        sacc[mt][t][1] = ex2f(sacc[mt][t][1] - mn0);
        sacc[mt][t][2] = ex2f(sacc[mt][t][2] - mn1);
        sacc[mt][t][3] = ex2f(sacc[mt][t][3] - mn1);
        rs0 += sacc[mt][t][0] + sacc[mt][t][1];
        rs1 += sacc[mt][t][2] + sacc[mt][t][3];
      }
#pragma unroll
      for (int off = 1; off <= 2; off <<= 1) {
        rs0 += __shfl_xor_sync(0xffffffffu, rs0, off);
        rs1 += __shfl_xor_sync(0xffffffffu, rs1, off);
      }
      l_i[mt][0] = l_i[mt][0] * corr0 + rs0;
      l_i[mt][1] = l_i[mt][1] * corr1 + rs1;

#pragma unroll
      for (int t = 0; t < 8; t++) {
        oacc[mt][t][0] *= corr0; oacc[mt][t][1] *= corr0;
        oacc[mt][t][2] *= corr1; oacc[mt][t][3] *= corr1;
      }
    }

    // --- O += P V: A-frag = accumulator {c0,c2,c1,c3}; V unpermuted ---
#pragma unroll
    for (int j = 0; j < 8; j++) {
      uint32_t af0[4] = {__float_as_uint(sacc[0][j][0]),
                         __float_as_uint(sacc[0][j][2]),
                         __float_as_uint(sacc[0][j][1]),
                         __float_as_uint(sacc[0][j][3])};
      uint32_t af1[4] = {__float_as_uint(sacc[1][j][0]),
                         __float_as_uint(sacc[1][j][2]),
                         __float_as_uint(sacc[1][j][1]),
                         __float_as_uint(sacc[1][j][3])};
#pragma unroll
      for (int t = 0; t < 8; t++) {
        float2 vv = vp[(t * 8 + g) * (KVSTRIDE / 2) + j * 4 + tg];
        uint32_t bf[2] = {__float_as_uint(vv.x), __float_as_uint(vv.y)};
        mma_16n8k8(oacc[0][t], af0, bf);
        mma_16n8k8(oacc[1][t], af1, bf);
      }
    }
    __syncthreads();
  }

  // --- Epilogue per m-tile: ctx = tf32(O / l), coalesced float2 stores ---
#pragma unroll
  for (int mt = 0; mt < 2; mt++) {
    const int q0 = qb * 128 + m0 + mt * 16 + g;
    float inv0 = 1.f / l_i[mt][0];
    float inv1 = 1.f / l_i[mt][1];
    float* cp0 = g_ctx + ((size_t)b * CN + q0) * CD + h * CKD;
#pragma unroll
    for (int t = 0; t < 8; t++) {
      *(float2*)(cp0 + t * 8 + 2 * tg) =
          make_float2(tf32_rna(oacc[mt][t][0] * inv0),
                      tf32_rna(oacc[mt][t][1] * inv0));
      *(float2*)(cp0 + (size_t)8 * CD + t * 8 + 2 * tg) =
          make_float2(tf32_rna(oacc[mt][t][2] * inv1),
                      tf32_rna(oacc[mt][t][3] * inv1));
    }
  }
}

// ---------------------------------------------------------------------------

extern "C" void kernel_launch(void* const* d_in, const int* in_sizes, int n_in,
                              void* d_out, int out_size) {
  const float* x = (const float*)d_in[0];
  const float* leadlag_bias = (const float*)d_in[1];
  const float* Wq = (const float*)d_in[2];
  const float* Wk = (const float*)d_in[3];
  const float* Wv = (const float*)d_in[4];
  const float* Wo = (const float*)d_in[5];
  const float* bias_scale = (const float*)d_in[6];
  float* out = (float*)d_out;

  (void)in_sizes; (void)n_in; (void)out_size;

  static int attr_set = 0;
  if (!attr_set) {
    cudaFuncSetAttribute(attn_mma_kernel,
                         cudaFuncAttributeMaxDynamicSharedMemorySize,
                         ATTN_SMEM_BYTES);
    cudaFuncSetAttribute(qkv_mma_kernel,
                         cudaFuncAttributeMaxDynamicSharedMemorySize,
                         GEMM_SMEM_BYTES);
    cudaFuncSetAttribute(out_mma_kernel,
                         cudaFuncAttributeMaxDynamicSharedMemorySize,
                         GEMM_SMEM_BYTES);
    attr_set = 1;
  }

  prep_x_kernel<<<CM * CD / 1024, 256>>>(x);
  transpose_w_kernel<<<dim3(CD / 32, CD / 32, 4), dim3(32, 8)>>>(Wq, Wk, Wv, Wo);
  qkv_mma_kernel<<<dim3(CD / 128, CM / 128, 3), 256, GEMM_SMEM_BYTES>>>();
  attn_mma_kernel<<<dim3(CN / 128, CH, CB), 128, ATTN_SMEM_BYTES>>>(
      leadlag_bias, bias_scale);
  out_mma_kernel<<<dim3(CD / 128, CM / 128, 1), 256, GEMM_SMEM_BYTES>>>(out);
}